// round 14
// baseline (speedup 1.0000x reference)
#include <cuda_runtime.h>
#include <cuda_fp16.h>
#include <math.h>
#include <stdint.h>

#define H_ 64
#define W_ 64
#define DIM 384
#define NHEADS 12
#define HDIM 32
#define WSZ 7
#define NTOK 49
#define NWIN 400
#define TOK 19600
#define BATCH 4
#define HW 4096
#define HID 1536
#define ATTN_SCALE 0.17677669529663689f
#define LN_EPS 1e-5f

// ---------------- scratch (device globals) ----------------
__device__ __half g_hA[TOK * DIM];
__device__ __half g_hB[(size_t)BATCH * HW * HID > (size_t)TOK * 3 * DIM
                       ? (size_t)BATCH * HW * HID : (size_t)TOK * 3 * DIM];
__device__ float g_x1[BATCH * HW * DIM];
__device__ float g_x2[BATCH * HW * DIM];
__device__ float g_cw[9 * DIM];   // conv weights reshaped [9][DIM]
#define WT_QKV_OFF 0
#define WT_PROJ_OFF (1152*384)
#define WT_FC1_OFF  (WT_PROJ_OFF + 384*384)
#define WT_FC2_OFF  (WT_FC1_OFF + 1536*384)
__device__ __half g_hw[WT_FC2_OFF + 384*1536];

// ---------------- helpers ----------------
__device__ __forceinline__ uint32_t smem_u32(const void* p) {
    uint32_t a;
    asm("{ .reg .u64 t; cvta.to.shared.u64 t, %1; cvt.u32.u64 %0, t; }" : "=r"(a) : "l"(p));
    return a;
}
__device__ __forceinline__ void cp_async16(uint32_t dst, const void* src, int srcbytes) {
    asm volatile("cp.async.cg.shared.global [%0], [%1], 16, %2;"
                 :: "r"(dst), "l"(src), "r"(srcbytes));
}
#define CP_COMMIT() asm volatile("cp.async.commit_group;" ::: "memory")
#define CP_WAIT1()  asm volatile("cp.async.wait_group 1;" ::: "memory")
#define CP_WAIT0()  asm volatile("cp.async.wait_group 0;" ::: "memory")

__device__ __forceinline__ void mma_f16(float* c, const uint32_t* a, const uint32_t* b) {
    asm volatile(
        "mma.sync.aligned.m16n8k16.row.col.f32.f16.f16.f32 "
        "{%0,%1,%2,%3}, {%4,%5,%6,%7}, {%8,%9}, {%0,%1,%2,%3};"
        : "+f"(c[0]), "+f"(c[1]), "+f"(c[2]), "+f"(c[3])
        : "r"(a[0]), "r"(a[1]), "r"(a[2]), "r"(a[3]), "r"(b[0]), "r"(b[1]));
}
__device__ __forceinline__ void ldsm4(uint32_t& r0, uint32_t& r1, uint32_t& r2, uint32_t& r3,
                                      uint32_t addr) {
    asm volatile("ldmatrix.sync.aligned.m8n8.x4.shared.b16 {%0,%1,%2,%3}, [%4];"
                 : "=r"(r0), "=r"(r1), "=r"(r2), "=r"(r3) : "r"(addr));
}
__device__ __forceinline__ uint32_t packh2(float x, float y) {
    __half2 h = __floats2half2_rn(x, y);
    return *(uint32_t*)&h;
}

// ---------------- fp16 tensor-core GEMM (ldmatrix inner loop) ----------------
#define BM 128
#define BN 128
#define BK 32
#define PADH 40
template <int EPI>
__global__ __launch_bounds__(256)
void mma_gemm(const __half* __restrict__ A, const __half* __restrict__ WT,
              const float* __restrict__ bias, const float* __restrict__ res,
              float* __restrict__ C, int M, int N, int K) {
    __shared__ __half As[2][BM * PADH];
    __shared__ __half Bs[2][BN * PADH];
    int tid = threadIdx.x;
    int lane = tid & 31, wid = tid >> 5;
    int wm = wid & 1, wn = wid >> 1;
    int row0 = blockIdx.y * BM, col0 = blockIdx.x * BN;
    int g4 = lane >> 2, t4 = lane & 3;

    float acc[4][4][4] = {};
    uint32_t sA[2] = { smem_u32(As[0]), smem_u32(As[1]) };
    uint32_t sB[2] = { smem_u32(Bs[0]), smem_u32(Bs[1]) };
    int nk = K / BK;

    // ldmatrix lane address offsets (bytes)
    int lrA = ((lane >> 3) & 1) * 8 + (lane & 7);
    int lcA = (lane >> 4) * 8;
    int lrB = ((lane >> 4) & 1) * 8 + (lane & 7);
    int lcB = ((lane >> 3) & 1) * 8;
    uint32_t aOff[4], bOff[2];
    #pragma unroll
    for (int mi = 0; mi < 4; mi++)
        aOff[mi] = (uint32_t)(((wm * 64 + mi * 16 + lrA) * PADH + lcA) * 2);
    #pragma unroll
    for (int p = 0; p < 2; p++)
        bOff[p] = (uint32_t)(((wn * 32 + p * 16 + lrB) * PADH + lcB) * 2);

    #define STAGE(buf, k0) do { \
        int _k0 = (k0); \
        _Pragma("unroll") \
        for (int i = 0; i < 2; i++) { \
            int idx = tid + i * 256; \
            int r = idx >> 2, c = idx & 3; \
            int gr = row0 + r; \
            uint32_t d = sA[buf] + (uint32_t)(r * PADH + c * 8) * 2u; \
            cp_async16(d, A + (size_t)gr * K + _k0 + c * 8, gr < M ? 16 : 0); \
        } \
        _Pragma("unroll") \
        for (int i = 0; i < 2; i++) { \
            int idx = tid + i * 256; \
            int r = idx >> 2, c = idx & 3; \
            uint32_t d = sB[buf] + (uint32_t)(r * PADH + c * 8) * 2u; \
            cp_async16(d, WT + (size_t)(col0 + r) * K + _k0 + c * 8, 16); \
        } \
        CP_COMMIT(); \
    } while (0)

    STAGE(0, 0);
    for (int t = 0; t < nk; t++) {
        int buf = t & 1;
        if (t + 1 < nk) { STAGE(buf ^ 1, (t + 1) * BK); CP_WAIT1(); }
        else            { CP_WAIT0(); }
        __syncthreads();

        #pragma unroll
        for (int kk = 0; kk < BK; kk += 16) {
            uint32_t af[4][4], bf[4][2];
            #pragma unroll
            for (int mi = 0; mi < 4; mi++)
                ldsm4(af[mi][0], af[mi][1], af[mi][2], af[mi][3],
                      sA[buf] + aOff[mi] + kk * 2);
            #pragma unroll
            for (int p = 0; p < 2; p++)
                ldsm4(bf[2 * p][0], bf[2 * p][1], bf[2 * p + 1][0], bf[2 * p + 1][1],
                      sB[buf] + bOff[p] + kk * 2);
            #pragma unroll
            for (int mi = 0; mi < 4; mi++)
                #pragma unroll
                for (int nj = 0; nj < 4; nj++)
                    mma_f16(acc[mi][nj], af[mi], bf[nj]);
        }
        __syncthreads();
    }

    __half* Ch = (__half*)C;
    #pragma unroll
    for (int mi = 0; mi < 4; mi++) {
        #pragma unroll
        for (int half_ = 0; half_ < 2; half_++) {
            int r = row0 + wm * 64 + mi * 16 + g4 + half_ * 8;
            if (r >= M) continue;
            size_t obase = 0;
            bool valid = true;
            if (EPI == 1) {
                int w = r / NTOK, n = r % NTOK;
                int bb = w / 100, wh = (w / 10) % 10, ww = w % 10;
                int rr = wh * WSZ + n / WSZ;
                int cc = ww * WSZ + n % WSZ;
                valid = (rr < H_) && (cc < W_);
                if (valid) obase = ((size_t)bb * HW + (size_t)rr * W_ + cc) * DIM;
            }
            #pragma unroll
            for (int nj = 0; nj < 4; nj++) {
                int cn = col0 + wn * 32 + nj * 8 + 2 * t4;
                float v0 = acc[mi][nj][half_ * 2 + 0] + bias[cn];
                float v1 = acc[mi][nj][half_ * 2 + 1] + bias[cn + 1];
                if (EPI == 0) {
                    *(__half2*)(Ch + (size_t)r * N + cn) = __floats2half2_rn(v0, v1);
                } else if (EPI == 1) {
                    if (valid) {
                        float2 rr2 = *(const float2*)(res + obase + cn);
                        *(float2*)(C + obase + cn) = make_float2(v0 + rr2.x, v1 + rr2.y);
                    }
                } else if (EPI == 2) {
                    v0 = 0.5f * v0 * (1.f + erff(v0 * 0.70710678118654752f));
                    v1 = 0.5f * v1 * (1.f + erff(v1 * 0.70710678118654752f));
                    *(__half2*)(Ch + (size_t)r * N + cn) = __floats2half2_rn(v0, v1);
                } else {
                    float2 rr2 = *(const float2*)(res + (size_t)r * N + cn);
                    *(float2*)(C + (size_t)r * N + cn) = make_float2(v0 + rr2.x, v1 + rr2.y);
                }
            }
        }
    }
}

// -------- merged weight transpose (+ conv weight reshape), one launch -------
__global__ void transpose_all(const float* __restrict__ qkv_w,
                              const float* __restrict__ proj_w,
                              const float* __restrict__ fc1_w,
                              const float* __restrict__ fc2_w,
                              const float* __restrict__ conv_w,
                              __half* __restrict__ wt) {
    __shared__ float t[32][33];
    int b = blockIdx.x;
    int tx = threadIdx.x, ty = threadIdx.y;
    if (b == 1728) {   // conv weight reshape [DIM][9] -> [9][DIM]
        int tt = ty * 32 + tx;
        for (int i = tt; i < 9 * DIM; i += 256) {
            int ch = i / 9, k = i % 9;
            g_cw[k * DIM + ch] = conv_w[i];
        }
        return;
    }
    const float* W; __half* WT; int K, N, tt;
    if (b < 432)       { W = qkv_w;  WT = wt + WT_QKV_OFF;  K = 384;  N = 1152; tt = b; }
    else if (b < 576)  { W = proj_w; WT = wt + WT_PROJ_OFF; K = 384;  N = 384;  tt = b - 432; }
    else if (b < 1152) { W = fc1_w;  WT = wt + WT_FC1_OFF;  K = 384;  N = 1536; tt = b - 576; }
    else               { W = fc2_w;  WT = wt + WT_FC2_OFF;  K = 1536; N = 384;  tt = b - 1152; }
    int nx = N / 32;
    int n0 = (tt % nx) * 32, k0 = (tt / nx) * 32;
    #pragma unroll
    for (int i = 0; i < 32; i += 8)
        t[ty + i][tx] = W[(size_t)(k0 + ty + i) * N + n0 + tx];
    __syncthreads();
    #pragma unroll
    for (int i = 0; i < 32; i += 8)
        WT[(size_t)(n0 + ty + i) * K + k0 + tx] = __float2half(t[tx][ty + i]);
}

// ---------------- block reduce (128 threads) ----------------
__device__ __forceinline__ void blockReduce2_128(float& s, float& q) {
    __shared__ float sh[8];
    int lane = threadIdx.x & 31, warp = threadIdx.x >> 5;
    #pragma unroll
    for (int o = 16; o > 0; o >>= 1) {
        s += __shfl_down_sync(0xffffffffu, s, o);
        q += __shfl_down_sync(0xffffffffu, q, o);
    }
    if (lane == 0) { sh[warp] = s; sh[4 + warp] = q; }
    __syncthreads();
    if (threadIdx.x == 0) {
        float a = 0.f, b = 0.f;
        #pragma unroll
        for (int i = 0; i < 4; i++) { a += sh[i]; b += sh[4 + i]; }
        sh[0] = a; sh[4] = b;
    }
    __syncthreads();
    s = sh[0]; q = sh[4];
    __syncthreads();
}

// ---------------- LN1 + window gather -> half ----------------
__global__ void ln1_win_kernel(const float* __restrict__ x,
                               const float* __restrict__ g,
                               const float* __restrict__ b) {
    int t = blockIdx.x;
    int w = t / NTOK, n = t % NTOK;
    int bb = w / 100, wh = (w / 10) % 10, ww = w % 10;
    int r = wh * WSZ + n / WSZ;
    int c = ww * WSZ + n % WSZ;
    __half* out = g_hA + (size_t)t * DIM;
    if (r >= H_ || c >= W_) {
        for (int ch = threadIdx.x; ch < DIM; ch += 128) out[ch] = __float2half(b[ch]);
        return;
    }
    const float* row = x + ((size_t)bb * HW + (size_t)r * W_ + c) * DIM;
    float v0 = row[threadIdx.x];
    float v1 = row[threadIdx.x + 128];
    float v2 = row[threadIdx.x + 256];
    float s = v0 + v1 + v2;
    float q = v0 * v0 + v1 * v1 + v2 * v2;
    blockReduce2_128(s, q);
    float mean = s * (1.f / DIM);
    float var = q * (1.f / DIM) - mean * mean;
    float rs = rsqrtf(var + LN_EPS);
    int ch = threadIdx.x;
    out[ch]       = __float2half((v0 - mean) * rs * g[ch]       + b[ch]);
    out[ch + 128] = __float2half((v1 - mean) * rs * g[ch + 128] + b[ch + 128]);
    out[ch + 256] = __float2half((v2 - mean) * rs * g[ch + 256] + b[ch + 256]);
}

// ---------------- attention via mma.sync: warp-pair per (window, head) ------
#define AUNITS 4
#define UNIT_HALVES 7424   // Qs 64x40 + Ks 64x40 + Vt 32x72
__global__ __launch_bounds__(256)
void attn_mma(const float* __restrict__ attn_bias) {
    extern __shared__ __half smh[];
    __shared__ unsigned char d7[64], m7[64];
    int tid = threadIdx.x;
    int unit = tid >> 6;
    int u_tid = tid & 63;
    int lane = tid & 31;
    int wh = (tid >> 5) & 1;
    int g4 = lane >> 2, t4 = lane & 3;
    int gidx = blockIdx.x * AUNITS + unit;
    int w = gidx / NHEADS, h = gidx % NHEADS;

    __half* Qs = smh + unit * UNIT_HALVES;
    __half* Ks = Qs + 2560;
    __half* Vt = Ks + 2560;           // 32 rows (d) x 72 halves (m + pad)
    float* bsm = (float*)(smh + 4 * UNIT_HALVES) + unit * 49;

    if (tid < 64) { d7[tid] = (unsigned char)(tid / 7); m7[tid] = (unsigned char)(tid % 7); }

    // zero ONLY V's padded m-columns (halves 48..63 of each d-row):
    // P is exactly 0 there, but 0 * NaN = NaN, so V pad must be finite.
    // Q/K pad rows stay uninitialized: every S element is overwritten (v= / -1e30).
    for (int i = u_tid; i < 256; i += 64) {
        int row = i >> 3, wc = 24 + (i & 7);
        ((uint32_t*)Vt)[row * 36 + wc] = 0u;
    }
    __syncthreads();

    // fill Q, K (row n, 32 halves) and V transposed (row d, col m)
    const uint32_t* qkvw = (const uint32_t*)g_hB;
    for (int i = u_tid; i < NTOK * 16; i += 64) {
        int n = i >> 4, d2 = i & 15;
        size_t base = ((size_t)(w * NTOK + n) * 1152 + h * 96) >> 1;
        uint32_t qw = qkvw[base + d2];
        uint32_t kw = qkvw[base + 16 + d2];
        uint32_t vw = qkvw[base + 32 + d2];
        ((uint32_t*)Qs)[n * 20 + d2] = qw;
        ((uint32_t*)Ks)[n * 20 + d2] = kw;
        __half2 vv = *(__half2*)&vw;
        Vt[(2 * d2) * 72 + n] = __low2half(vv);
        Vt[(2 * d2 + 1) * 72 + n] = __high2half(vv);
    }
    if (u_tid < NTOK) bsm[u_tid] = attn_bias[h * NTOK + u_tid];
    __syncthreads();

    // ---- scores: 2 mi-tiles x 8 nj-tiles, K=32 ----
    const uint32_t* Qw = (const uint32_t*)Qs;
    const uint32_t* Kw = (const uint32_t*)Ks;
    float s[2][8][4] = {};
    #pragma unroll
    for (int kk = 0; kk < 2; kk++) {
        uint32_t a[2][4], b[8][2];
        #pragma unroll
        for (int mi = 0; mi < 2; mi++) {
            int r = wh * 32 + mi * 16 + g4;
            a[mi][0] = Qw[r * 20 + kk * 8 + t4];
            a[mi][1] = Qw[(r + 8) * 20 + kk * 8 + t4];
            a[mi][2] = Qw[r * 20 + kk * 8 + t4 + 4];
            a[mi][3] = Qw[(r + 8) * 20 + kk * 8 + t4 + 4];
        }
        #pragma unroll
        for (int nj = 0; nj < 8; nj++) {
            int n = nj * 8 + g4;
            b[nj][0] = Kw[n * 20 + kk * 8 + t4];
            b[nj][1] = Kw[n * 20 + kk * 8 + t4 + 4];
        }
        #pragma unroll
        for (int mi = 0; mi < 2; mi++)
            #pragma unroll
            for (int nj = 0; nj < 8; nj++)
                mma_f16(s[mi][nj], a[mi], b[nj]);
    }

    // ---- bias + mask + softmax in fragments ----
    #pragma unroll
    for (int mi = 0; mi < 2; mi++) {
        #pragma unroll
        for (int hf = 0; hf < 2; hf++) {
            int row = wh * 32 + mi * 16 + hf * 8 + g4;
            bool rowok = row < NTOK;
            int rd = d7[row], rm = m7[row];
            float mx = -1e30f;
            #pragma unroll
            for (int nj = 0; nj < 8; nj++) {
                #pragma unroll
                for (int e = 0; e < 2; e++) {
                    int col = nj * 8 + 2 * t4 + e;
                    float v = s[mi][nj][hf * 2 + e] * ATTN_SCALE;
                    if (rowok && col < NTOK) {
                        int dr = abs(rd - (int)d7[col]);
                        int dc = abs(rm - (int)m7[col]);
                        v += bsm[dr * 7 + dc];
                    } else v = -1e30f;
                    s[mi][nj][hf * 2 + e] = v;
                    mx = fmaxf(mx, v);
                }
            }
            mx = fmaxf(mx, __shfl_xor_sync(0xffffffffu, mx, 1));
            mx = fmaxf(mx, __shfl_xor_sync(0xffffffffu, mx, 2));
            if (mx < -1e29f) mx = 0.f;
            float sum = 0.f;
            #pragma unroll
            for (int nj = 0; nj < 8; nj++) {
                #pragma unroll
                for (int e = 0; e < 2; e++) {
                    float ev = __expf(s[mi][nj][hf * 2 + e] - mx);
                    s[mi][nj][hf * 2 + e] = ev;
                    sum += ev;
                }
            }
            sum += __shfl_xor_sync(0xffffffffu, sum, 1);
            sum += __shfl_xor_sync(0xffffffffu, sum, 2);
            float inv = rowok ? 1.f / sum : 0.f;
            #pragma unroll
            for (int nj = 0; nj < 8; nj++) {
                s[mi][nj][hf * 2 + 0] *= inv;
                s[mi][nj][hf * 2 + 1] *= inv;
            }
        }
    }

    // ---- O = P @ V ----
    float o[2][4][4] = {};
    const uint32_t* Vw = (const uint32_t*)Vt;
    #pragma unroll
    for (int kkA = 0; kkA < 4; kkA++) {
        uint32_t b[4][2];
        #pragma unroll
        for (int njd = 0; njd < 4; njd++) {
            int d = njd * 8 + g4;
            b[njd][0] = Vw[d * 36 + kkA * 8 + t4];
            b[njd][1] = Vw[d * 36 + kkA * 8 + t4 + 4];
        }
        #pragma unroll
        for (int mi = 0; mi < 2; mi++) {
            uint32_t a[4];
            a[0] = packh2(s[mi][2 * kkA][0],     s[mi][2 * kkA][1]);
            a[1] = packh2(s[mi][2 * kkA][2],     s[mi][2 * kkA][3]);
            a[2] = packh2(s[mi][2 * kkA + 1][0], s[mi][2 * kkA + 1][1]);
            a[3] = packh2(s[mi][2 * kkA + 1][2], s[mi][2 * kkA + 1][3]);
            #pragma unroll
            for (int njd = 0; njd < 4; njd++)
                mma_f16(o[mi][njd], a, b[njd]);
        }
    }

    // ---- store valid rows ----
    #pragma unroll
    for (int mi = 0; mi < 2; mi++) {
        #pragma unroll
        for (int hf = 0; hf < 2; hf++) {
            int row = wh * 32 + mi * 16 + hf * 8 + g4;
            if (row >= NTOK) continue;
            __half* dst = g_hA + ((size_t)(w * NTOK + row)) * DIM + h * HDIM;
            #pragma unroll
            for (int njd = 0; njd < 4; njd++) {
                int d = njd * 8 + 2 * t4;
                *(__half2*)(dst + d) =
                    __floats2half2_rn(o[mi][njd][hf * 2 + 0], o[mi][njd][hf * 2 + 1]);
            }
        }
    }
}

// ---------- depthwise conv + BN + LN2, one block per image row -------------
// thread t: pixel = t>>2 (column), channel lane = t&3 (96 ch each)
__global__ __launch_bounds__(256)
void conv_bn_ln_kernel(const float* __restrict__ bn_g,
                       const float* __restrict__ bn_b,
                       const float* __restrict__ bn_mean,
                       const float* __restrict__ bn_var,
                       const float* __restrict__ ln_g,
                       const float* __restrict__ ln_b) {
    int t = threadIdx.x;
    int c = t >> 2;             // pixel column 0..63
    int l4 = t & 3;             // channel quarter
    int bb = blockIdx.x >> 6;
    int r = blockIdx.x & 63;
    const float* base = g_x1 + (size_t)bb * HW * DIM;
    size_t pbase = ((size_t)bb * HW + r * 64 + c) * DIM;
    float s = 0.f, q = 0.f;
    #pragma unroll 4
    for (int cg = 0; cg < 24; cg++) {
        int ch = l4 * 96 + cg * 4;
        float4 acc = make_float4(0.f, 0.f, 0.f, 0.f);
        #pragma unroll
        for (int kh = 0; kh < 3; kh++) {
            int rr = r + kh - 1;
            if (rr < 0 || rr >= H_) continue;
            #pragma unroll
            for (int kw = 0; kw < 3; kw++) {
                int cc = c + kw - 1;
                if (cc < 0 || cc >= W_) continue;
                float4 v = *(const float4*)(base + ((size_t)rr * W_ + cc) * DIM + ch);
                float4 wv = *(const float4*)(g_cw + (kh * 3 + kw) * DIM + ch);
                acc.x += v.x * wv.x; acc.y += v.y * wv.y;
                acc.z += v.z * wv.z; acc.w += v.w * wv.w;
            }
        }
        float4 mn = *(const float4*)(bn_mean + ch);
        float4 vr = *(const float4*)(bn_var + ch);
        float4 gg = *(const float4*)(bn_g + ch);
        float4 bbv = *(const float4*)(bn_b + ch);
        float4 o;
        o.x = (acc.x - mn.x) * rsqrtf(vr.x + LN_EPS) * gg.x + bbv.x;
        o.y = (acc.y - mn.y) * rsqrtf(vr.y + LN_EPS) * gg.y + bbv.y;
        o.z = (acc.z - mn.z) * rsqrtf(vr.z + LN_EPS) * gg.z + bbv.z;
        o.w = (acc.w - mn.w) * rsqrtf(vr.w + LN_EPS) * gg.w + bbv.w;
        *(float4*)(g_x2 + pbase + ch) = o;
        s += o.x + o.y + o.z + o.w;
        q += o.x * o.x + o.y * o.y + o.z * o.z + o.w * o.w;
    }
    // reduce over the 4 lanes of this pixel
    s += __shfl_xor_sync(0xffffffffu, s, 1);
    s += __shfl_xor_sync(0xffffffffu, s, 2);
    q += __shfl_xor_sync(0xffffffffu, q, 1);
    q += __shfl_xor_sync(0xffffffffu, q, 2);
    float mean = s * (1.f / DIM);
    float var = q * (1.f / DIM) - mean * mean;
    float rs = rsqrtf(var + LN_EPS);
    __half* outp = g_hA + pbase;
    #pragma unroll 4
    for (int cg = 0; cg < 24; cg++) {
        int ch = l4 * 96 + cg * 4;
        float4 o = *(const float4*)(g_x2 + pbase + ch);   // L1-hot reload
        float4 lg = *(const float4*)(ln_g + ch);
        float4 lb = *(const float4*)(ln_b + ch);
        *(__half2*)(outp + ch)     = __floats2half2_rn((o.x - mean) * rs * lg.x + lb.x,
                                                       (o.y - mean) * rs * lg.y + lb.y);
        *(__half2*)(outp + ch + 2) = __floats2half2_rn((o.z - mean) * rs * lg.z + lb.z,
                                                       (o.w - mean) * rs * lg.w + lb.w);
    }
}

// ---------------- launch ----------------
#define ATTN_SMEM (4 * UNIT_HALVES * 2 + 4 * 49 * 4 + 16)
extern "C" void kernel_launch(void* const* d_in, const int* in_sizes, int n_in,
                              void* d_out, int out_size) {
    const float* x       = (const float*)d_in[0];
    const float* ln1_g   = (const float*)d_in[1];
    const float* ln1_b   = (const float*)d_in[2];
    const float* qkv_w   = (const float*)d_in[3];
    const float* qkv_b   = (const float*)d_in[4];
    const float* proj_w  = (const float*)d_in[5];
    const float* proj_b  = (const float*)d_in[6];
    const float* attn_b  = (const float*)d_in[7];
    const float* conv_w  = (const float*)d_in[8];
    const float* bn_g    = (const float*)d_in[9];
    const float* bn_b    = (const float*)d_in[10];
    const float* bn_mean = (const float*)d_in[11];
    const float* bn_var  = (const float*)d_in[12];
    const float* ln2_g   = (const float*)d_in[13];
    const float* ln2_b   = (const float*)d_in[14];
    const float* fc1_w   = (const float*)d_in[15];
    const float* fc1_b   = (const float*)d_in[16];
    const float* fc2_w   = (const float*)d_in[17];
    const float* fc2_b   = (const float*)d_in[18];
    float* out = (float*)d_out;

    __half *phA, *phB, *phW;
    float *px1, *px2;
    cudaGetSymbolAddress((void**)&phA, g_hA);
    cudaGetSymbolAddress((void**)&phB, g_hB);
    cudaGetSymbolAddress((void**)&phW, g_hw);
    cudaGetSymbolAddress((void**)&px1, g_x1);
    cudaGetSymbolAddress((void**)&px2, g_x2);

    cudaFuncSetAttribute(attn_mma, cudaFuncAttributeMaxDynamicSharedMemorySize, ATTN_SMEM);

    // 0. all weight transposes + conv reshape, one launch
    transpose_all<<<1729, dim3(32, 8)>>>(qkv_w, proj_w, fc1_w, fc2_w, conv_w, phW);

    // 1. LN1 + window partition -> hA (half)
    ln1_win_kernel<<<TOK, 128>>>(x, ln1_g, ln1_b);

    // 2. QKV GEMM -> hB (half)
    mma_gemm<0><<<dim3(1152 / 128, (TOK + 127) / 128), 256>>>(
        phA, phW + WT_QKV_OFF, qkv_b, nullptr, (float*)phB, TOK, 1152, 384);

    // 3. attention (tensor-core) -> hA (half)
    attn_mma<<<NWIN * NHEADS / AUNITS, 256, ATTN_SMEM>>>(attn_b);

    // 4. proj GEMM + un-window + residual -> x1 (f32)
    mma_gemm<1><<<dim3(384 / 128, (TOK + 127) / 128), 256>>>(
        phA, phW + WT_PROJ_OFF, proj_b, x, px1, TOK, 384, 384);

    // 5. depthwise conv + BN -> x2 (f32), fused LN2 -> hA (half)
    conv_bn_ln_kernel<<<BATCH * H_, 256>>>(bn_g, bn_b, bn_mean, bn_var, ln2_g, ln2_b);

    // 6. FC1 + GELU -> hB (half h1)
    mma_gemm<2><<<dim3(1536 / 128, (BATCH * HW) / 128), 256>>>(
        phA, phW + WT_FC1_OFF, fc1_b, nullptr, (float*)phB, BATCH * HW, 1536, 384);

    // 7. FC2 + residual -> d_out (f32)
    mma_gemm<3><<<dim3(384 / 128, (BATCH * HW) / 128), 256>>>(
        phB, phW + WT_FC2_OFF, fc2_b, px2, out, BATCH * HW, 384, 1536);
}

// round 15
// speedup vs baseline: 1.8600x; 1.8600x over previous
#include <cuda_runtime.h>
#include <cuda_fp16.h>
#include <math.h>
#include <stdint.h>

#define H_ 64
#define W_ 64
#define DIM 384
#define NHEADS 12
#define HDIM 32
#define WSZ 7
#define NTOK 49
#define NWIN 400
#define TOK 19600
#define BATCH 4
#define HW 4096
#define HID 1536
#define ATTN_SCALE 0.17677669529663689f
#define LN_EPS 1e-5f

// ---------------- scratch (device globals) ----------------
__device__ __half g_hA[TOK * DIM];
__device__ __half g_hB[(size_t)BATCH * HW * HID > (size_t)TOK * 3 * DIM
                       ? (size_t)BATCH * HW * HID : (size_t)TOK * 3 * DIM];
__device__ float g_x1[BATCH * HW * DIM];
__device__ float g_x2[BATCH * HW * DIM];
#define WT_QKV_OFF 0
#define WT_PROJ_OFF (1152*384)
#define WT_FC1_OFF  (WT_PROJ_OFF + 384*384)
#define WT_FC2_OFF  (WT_FC1_OFF + 1536*384)
__device__ __half g_hw[WT_FC2_OFF + 384*1536];

// ---------------- helpers ----------------
__device__ __forceinline__ uint32_t smem_u32(const void* p) {
    uint32_t a;
    asm("{ .reg .u64 t; cvta.to.shared.u64 t, %1; cvt.u32.u64 %0, t; }" : "=r"(a) : "l"(p));
    return a;
}
__device__ __forceinline__ void cp_async16(uint32_t dst, const void* src, int srcbytes) {
    asm volatile("cp.async.cg.shared.global [%0], [%1], 16, %2;"
                 :: "r"(dst), "l"(src), "r"(srcbytes));
}
#define CP_COMMIT() asm volatile("cp.async.commit_group;" ::: "memory")
#define CP_WAIT1()  asm volatile("cp.async.wait_group 1;" ::: "memory")
#define CP_WAIT0()  asm volatile("cp.async.wait_group 0;" ::: "memory")

__device__ __forceinline__ void mma_f16(float* c, const uint32_t* a, const uint32_t* b) {
    asm volatile(
        "mma.sync.aligned.m16n8k16.row.col.f32.f16.f16.f32 "
        "{%0,%1,%2,%3}, {%4,%5,%6,%7}, {%8,%9}, {%0,%1,%2,%3};"
        : "+f"(c[0]), "+f"(c[1]), "+f"(c[2]), "+f"(c[3])
        : "r"(a[0]), "r"(a[1]), "r"(a[2]), "r"(a[3]), "r"(b[0]), "r"(b[1]));
}
__device__ __forceinline__ uint32_t packh2(float x, float y) {
    __half2 h = __floats2half2_rn(x, y);
    return *(uint32_t*)&h;
}

// ---------------- fp16 tensor-core GEMM (scalar-LDS fragments; known-good) ----
#define BM 128
#define BN 128
#define BK 32
#define PADH 40
template <int EPI>
__global__ __launch_bounds__(256)
void mma_gemm(const __half* __restrict__ A, const __half* __restrict__ WT,
              const float* __restrict__ bias, const float* __restrict__ res,
              float* __restrict__ C, int M, int N, int K) {
    __shared__ __half As[2][BM * PADH];
    __shared__ __half Bs[2][BN * PADH];
    int tid = threadIdx.x;
    int lane = tid & 31, wid = tid >> 5;
    int wm = wid & 1, wn = wid >> 1;
    int row0 = blockIdx.y * BM, col0 = blockIdx.x * BN;
    int g4 = lane >> 2, t4 = lane & 3;

    float acc[4][4][4] = {};
    uint32_t sA[2] = { smem_u32(As[0]), smem_u32(As[1]) };
    uint32_t sB[2] = { smem_u32(Bs[0]), smem_u32(Bs[1]) };
    int nk = K / BK;

    #define STAGE(buf, k0) do { \
        int _k0 = (k0); \
        _Pragma("unroll") \
        for (int i = 0; i < 2; i++) { \
            int idx = tid + i * 256; \
            int r = idx >> 2, c = idx & 3; \
            int gr = row0 + r; \
            uint32_t d = sA[buf] + (uint32_t)(r * PADH + c * 8) * 2u; \
            cp_async16(d, A + (size_t)gr * K + _k0 + c * 8, gr < M ? 16 : 0); \
        } \
        _Pragma("unroll") \
        for (int i = 0; i < 2; i++) { \
            int idx = tid + i * 256; \
            int r = idx >> 2, c = idx & 3; \
            uint32_t d = sB[buf] + (uint32_t)(r * PADH + c * 8) * 2u; \
            cp_async16(d, WT + (size_t)(col0 + r) * K + _k0 + c * 8, 16); \
        } \
        CP_COMMIT(); \
    } while (0)

    STAGE(0, 0);
    for (int t = 0; t < nk; t++) {
        int buf = t & 1;
        if (t + 1 < nk) { STAGE(buf ^ 1, (t + 1) * BK); CP_WAIT1(); }
        else            { CP_WAIT0(); }
        __syncthreads();

        const __half* as = As[buf];
        const __half* bs = Bs[buf];
        #pragma unroll
        for (int kk = 0; kk < BK; kk += 16) {
            uint32_t af[4][4], bf[4][2];
            #pragma unroll
            for (int mi = 0; mi < 4; mi++) {
                int m = wm * 64 + mi * 16 + g4;
                af[mi][0] = *(const uint32_t*)(as + m * PADH + kk + 2 * t4);
                af[mi][1] = *(const uint32_t*)(as + (m + 8) * PADH + kk + 2 * t4);
                af[mi][2] = *(const uint32_t*)(as + m * PADH + kk + 2 * t4 + 8);
                af[mi][3] = *(const uint32_t*)(as + (m + 8) * PADH + kk + 2 * t4 + 8);
            }
            #pragma unroll
            for (int nj = 0; nj < 4; nj++) {
                int n = wn * 32 + nj * 8 + g4;
                bf[nj][0] = *(const uint32_t*)(bs + n * PADH + kk + 2 * t4);
                bf[nj][1] = *(const uint32_t*)(bs + n * PADH + kk + 2 * t4 + 8);
            }
            #pragma unroll
            for (int mi = 0; mi < 4; mi++)
                #pragma unroll
                for (int nj = 0; nj < 4; nj++)
                    mma_f16(acc[mi][nj], af[mi], bf[nj]);
        }
        __syncthreads();
    }

    __half* Ch = (__half*)C;
    #pragma unroll
    for (int mi = 0; mi < 4; mi++) {
        #pragma unroll
        for (int half_ = 0; half_ < 2; half_++) {
            int r = row0 + wm * 64 + mi * 16 + g4 + half_ * 8;
            if (r >= M) continue;
            size_t obase = 0;
            bool valid = true;
            if (EPI == 1) {
                int w = r / NTOK, n = r % NTOK;
                int bb = w / 100, wh = (w / 10) % 10, ww = w % 10;
                int rr = wh * WSZ + n / WSZ;
                int cc = ww * WSZ + n % WSZ;
                valid = (rr < H_) && (cc < W_);
                if (valid) obase = ((size_t)bb * HW + (size_t)rr * W_ + cc) * DIM;
            }
            #pragma unroll
            for (int nj = 0; nj < 4; nj++) {
                int cn = col0 + wn * 32 + nj * 8 + 2 * t4;
                float v0 = acc[mi][nj][half_ * 2 + 0] + bias[cn];
                float v1 = acc[mi][nj][half_ * 2 + 1] + bias[cn + 1];
                if (EPI == 0) {
                    *(__half2*)(Ch + (size_t)r * N + cn) = __floats2half2_rn(v0, v1);
                } else if (EPI == 1) {
                    if (valid) {
                        float2 rr2 = *(const float2*)(res + obase + cn);
                        *(float2*)(C + obase + cn) = make_float2(v0 + rr2.x, v1 + rr2.y);
                    }
                } else if (EPI == 2) {
                    v0 = 0.5f * v0 * (1.f + erff(v0 * 0.70710678118654752f));
                    v1 = 0.5f * v1 * (1.f + erff(v1 * 0.70710678118654752f));
                    *(__half2*)(Ch + (size_t)r * N + cn) = __floats2half2_rn(v0, v1);
                } else {
                    float2 rr2 = *(const float2*)(res + (size_t)r * N + cn);
                    *(float2*)(C + (size_t)r * N + cn) = make_float2(v0 + rr2.x, v1 + rr2.y);
                }
            }
        }
    }
}

// ---------------- merged weight transpose: all 4 matrices, one launch -------
__global__ void transpose_all(const float* __restrict__ qkv_w,
                              const float* __restrict__ proj_w,
                              const float* __restrict__ fc1_w,
                              const float* __restrict__ fc2_w,
                              __half* __restrict__ wt) {
    __shared__ float t[32][33];
    int b = blockIdx.x;
    const float* W; __half* WT; int K, N, tt;
    if (b < 432)       { W = qkv_w;  WT = wt + WT_QKV_OFF;  K = 384;  N = 1152; tt = b; }
    else if (b < 576)  { W = proj_w; WT = wt + WT_PROJ_OFF; K = 384;  N = 384;  tt = b - 432; }
    else if (b < 1152) { W = fc1_w;  WT = wt + WT_FC1_OFF;  K = 384;  N = 1536; tt = b - 576; }
    else               { W = fc2_w;  WT = wt + WT_FC2_OFF;  K = 1536; N = 384;  tt = b - 1152; }
    int nx = N / 32;
    int n0 = (tt % nx) * 32, k0 = (tt / nx) * 32;
    int tx = threadIdx.x, ty = threadIdx.y;
    #pragma unroll
    for (int i = 0; i < 32; i += 8)
        t[ty + i][tx] = W[(size_t)(k0 + ty + i) * N + n0 + tx];
    __syncthreads();
    #pragma unroll
    for (int i = 0; i < 32; i += 8)
        WT[(size_t)(n0 + ty + i) * K + k0 + tx] = __float2half(t[tx][ty + i]);
}

// ---------------- block reduce (128 threads) ----------------
__device__ __forceinline__ void blockReduce2_128(float& s, float& q) {
    __shared__ float sh[8];
    int lane = threadIdx.x & 31, warp = threadIdx.x >> 5;
    #pragma unroll
    for (int o = 16; o > 0; o >>= 1) {
        s += __shfl_down_sync(0xffffffffu, s, o);
        q += __shfl_down_sync(0xffffffffu, q, o);
    }
    if (lane == 0) { sh[warp] = s; sh[4 + warp] = q; }
    __syncthreads();
    if (threadIdx.x == 0) {
        float a = 0.f, b = 0.f;
        #pragma unroll
        for (int i = 0; i < 4; i++) { a += sh[i]; b += sh[4 + i]; }
        sh[0] = a; sh[4] = b;
    }
    __syncthreads();
    s = sh[0]; q = sh[4];
    __syncthreads();
}

// ---------------- LN1 + window gather -> half ----------------
__global__ void ln1_win_kernel(const float* __restrict__ x,
                               const float* __restrict__ g,
                               const float* __restrict__ b) {
    int t = blockIdx.x;
    int w = t / NTOK, n = t % NTOK;
    int bb = w / 100, wh = (w / 10) % 10, ww = w % 10;
    int r = wh * WSZ + n / WSZ;
    int c = ww * WSZ + n % WSZ;
    __half* out = g_hA + (size_t)t * DIM;
    if (r >= H_ || c >= W_) {
        for (int ch = threadIdx.x; ch < DIM; ch += 128) out[ch] = __float2half(b[ch]);
        return;
    }
    const float* row = x + ((size_t)bb * HW + (size_t)r * W_ + c) * DIM;
    float v0 = row[threadIdx.x];
    float v1 = row[threadIdx.x + 128];
    float v2 = row[threadIdx.x + 256];
    float s = v0 + v1 + v2;
    float q = v0 * v0 + v1 * v1 + v2 * v2;
    blockReduce2_128(s, q);
    float mean = s * (1.f / DIM);
    float var = q * (1.f / DIM) - mean * mean;
    float rs = rsqrtf(var + LN_EPS);
    int ch = threadIdx.x;
    out[ch]       = __float2half((v0 - mean) * rs * g[ch]       + b[ch]);
    out[ch + 128] = __float2half((v1 - mean) * rs * g[ch + 128] + b[ch + 128]);
    out[ch + 256] = __float2half((v2 - mean) * rs * g[ch + 256] + b[ch + 256]);
}

// ---------------- attention via mma.sync: warp-pair per (window, head) ------
// ONLY change vs the 423.6us-benched version: zero V's pad columns only
// (every S element is overwritten by the mask pass; Q/K pads never read-as-math).
#define AUNITS 4
#define UNIT_HALVES 7424   // Qs 64x40 + Ks 64x40 + Vt 32x72
__global__ __launch_bounds__(256)
void attn_mma(const float* __restrict__ attn_bias) {
    extern __shared__ __half smh[];
    __shared__ unsigned char d7[64], m7[64];
    int tid = threadIdx.x;
    int unit = tid >> 6;
    int u_tid = tid & 63;
    int lane = tid & 31;
    int wh = (tid >> 5) & 1;
    int g4 = lane >> 2, t4 = lane & 3;
    int gidx = blockIdx.x * AUNITS + unit;
    int w = gidx / NHEADS, h = gidx % NHEADS;

    __half* Qs = smh + unit * UNIT_HALVES;
    __half* Ks = Qs + 2560;
    __half* Vt = Ks + 2560;           // 32 rows (d) x 72 halves (m + pad)
    float* bsm = (float*)(smh + 4 * UNIT_HALVES) + unit * 49;

    if (tid < 64) { d7[tid] = (unsigned char)(tid / 7); m7[tid] = (unsigned char)(tid % 7); }

    // zero ONLY V's padded m-columns (halves 48..63 of each d-row): P is 0
    // there, but 0 * garbage-NaN = NaN in the PV MMA, so V pad must be finite.
    for (int i = u_tid; i < 256; i += 64) {
        int row = i >> 3, wc = 24 + (i & 7);
        ((uint32_t*)Vt)[row * 36 + wc] = 0u;
    }
    __syncthreads();

    // fill Q, K (row n, 32 halves) and V transposed (row d, col m)
    const uint32_t* qkvw = (const uint32_t*)g_hB;
    for (int i = u_tid; i < NTOK * 16; i += 64) {
        int n = i >> 4, d2 = i & 15;
        size_t base = ((size_t)(w * NTOK + n) * 1152 + h * 96) >> 1;
        uint32_t qw = qkvw[base + d2];
        uint32_t kw = qkvw[base + 16 + d2];
        uint32_t vw = qkvw[base + 32 + d2];
        ((uint32_t*)Qs)[n * 20 + d2] = qw;
        ((uint32_t*)Ks)[n * 20 + d2] = kw;
        __half2 vv = *(__half2*)&vw;
        Vt[(2 * d2) * 72 + n] = __low2half(vv);
        Vt[(2 * d2 + 1) * 72 + n] = __high2half(vv);
    }
    if (u_tid < NTOK) bsm[u_tid] = attn_bias[h * NTOK + u_tid];
    __syncthreads();

    // ---- scores: 2 mi-tiles x 8 nj-tiles, K=32 ----
    const uint32_t* Qw = (const uint32_t*)Qs;
    const uint32_t* Kw = (const uint32_t*)Ks;
    float s[2][8][4] = {};
    #pragma unroll
    for (int kk = 0; kk < 2; kk++) {
        uint32_t a[2][4], b[8][2];
        #pragma unroll
        for (int mi = 0; mi < 2; mi++) {
            int r = wh * 32 + mi * 16 + g4;
            a[mi][0] = Qw[r * 20 + kk * 8 + t4];
            a[mi][1] = Qw[(r + 8) * 20 + kk * 8 + t4];
            a[mi][2] = Qw[r * 20 + kk * 8 + t4 + 4];
            a[mi][3] = Qw[(r + 8) * 20 + kk * 8 + t4 + 4];
        }
        #pragma unroll
        for (int nj = 0; nj < 8; nj++) {
            int n = nj * 8 + g4;
            b[nj][0] = Kw[n * 20 + kk * 8 + t4];
            b[nj][1] = Kw[n * 20 + kk * 8 + t4 + 4];
        }
        #pragma unroll
        for (int mi = 0; mi < 2; mi++)
            #pragma unroll
            for (int nj = 0; nj < 8; nj++)
                mma_f16(s[mi][nj], a[mi], b[nj]);
    }

    // ---- bias + mask + softmax in fragments ----
    #pragma unroll
    for (int mi = 0; mi < 2; mi++) {
        #pragma unroll
        for (int hf = 0; hf < 2; hf++) {
            int row = wh * 32 + mi * 16 + hf * 8 + g4;
            bool rowok = row < NTOK;
            int rd = d7[row], rm = m7[row];
            float mx = -1e30f;
            #pragma unroll
            for (int nj = 0; nj < 8; nj++) {
                #pragma unroll
                for (int e = 0; e < 2; e++) {
                    int col = nj * 8 + 2 * t4 + e;
                    float v = s[mi][nj][hf * 2 + e] * ATTN_SCALE;
                    if (rowok && col < NTOK) {
                        int dr = abs(rd - (int)d7[col]);
                        int dc = abs(rm - (int)m7[col]);
                        v += bsm[dr * 7 + dc];
                    } else v = -1e30f;
                    s[mi][nj][hf * 2 + e] = v;
                    mx = fmaxf(mx, v);
                }
            }
            mx = fmaxf(mx, __shfl_xor_sync(0xffffffffu, mx, 1));
            mx = fmaxf(mx, __shfl_xor_sync(0xffffffffu, mx, 2));
            if (mx < -1e29f) mx = 0.f;
            float sum = 0.f;
            #pragma unroll
            for (int nj = 0; nj < 8; nj++) {
                #pragma unroll
                for (int e = 0; e < 2; e++) {
                    float ev = __expf(s[mi][nj][hf * 2 + e] - mx);
                    s[mi][nj][hf * 2 + e] = ev;
                    sum += ev;
                }
            }
            sum += __shfl_xor_sync(0xffffffffu, sum, 1);
            sum += __shfl_xor_sync(0xffffffffu, sum, 2);
            float inv = rowok ? 1.f / sum : 0.f;
            #pragma unroll
            for (int nj = 0; nj < 8; nj++) {
                s[mi][nj][hf * 2 + 0] *= inv;
                s[mi][nj][hf * 2 + 1] *= inv;
            }
        }
    }

    // ---- O = P @ V ----
    float o[2][4][4] = {};
    const uint32_t* Vw = (const uint32_t*)Vt;
    #pragma unroll
    for (int kkA = 0; kkA < 4; kkA++) {
        uint32_t b[4][2];
        #pragma unroll
        for (int njd = 0; njd < 4; njd++) {
            int d = njd * 8 + g4;
            b[njd][0] = Vw[d * 36 + kkA * 8 + t4];
            b[njd][1] = Vw[d * 36 + kkA * 8 + t4 + 4];
        }
        #pragma unroll
        for (int mi = 0; mi < 2; mi++) {
            uint32_t a[4];
            a[0] = packh2(s[mi][2 * kkA][0],     s[mi][2 * kkA][1]);
            a[1] = packh2(s[mi][2 * kkA][2],     s[mi][2 * kkA][3]);
            a[2] = packh2(s[mi][2 * kkA + 1][0], s[mi][2 * kkA + 1][1]);
            a[3] = packh2(s[mi][2 * kkA + 1][2], s[mi][2 * kkA + 1][3]);
            #pragma unroll
            for (int njd = 0; njd < 4; njd++)
                mma_f16(o[mi][njd], a, b[njd]);
        }
    }

    // ---- store valid rows ----
    #pragma unroll
    for (int mi = 0; mi < 2; mi++) {
        #pragma unroll
        for (int hf = 0; hf < 2; hf++) {
            int row = wh * 32 + mi * 16 + hf * 8 + g4;
            if (row >= NTOK) continue;
            __half* dst = g_hA + ((size_t)(w * NTOK + row)) * DIM + h * HDIM;
            #pragma unroll
            for (int njd = 0; njd < 4; njd++) {
                int d = njd * 8 + 2 * t4;
                *(__half2*)(dst + d) =
                    __floats2half2_rn(o[mi][njd][hf * 2 + 0], o[mi][njd][hf * 2 + 1]);
            }
        }
    }
}

// ---------------- depthwise 3x3 conv + BN + fused LN2 (known-good) ----------
__global__ void conv_bn_ln_kernel(const float* __restrict__ w9,
                                  const float* __restrict__ bn_g,
                                  const float* __restrict__ bn_b,
                                  const float* __restrict__ bn_mean,
                                  const float* __restrict__ bn_var,
                                  const float* __restrict__ ln_g,
                                  const float* __restrict__ ln_b) {
    int p = blockIdx.x;
    int bb = p >> 12;
    int pos = p & 4095;
    int r = pos >> 6, c = pos & 63;
    const float* base = g_x1 + (size_t)bb * HW * DIM;
    float o[3];
    #pragma unroll
    for (int k = 0; k < 3; k++) {
        int ch = threadIdx.x + k * 128;
        float s = 0.f;
        #pragma unroll
        for (int kh = 0; kh < 3; kh++) {
            int rr = r + kh - 1;
            if (rr < 0 || rr >= H_) continue;
            #pragma unroll
            for (int kw = 0; kw < 3; kw++) {
                int cc = c + kw - 1;
                if (cc < 0 || cc >= W_) continue;
                s += base[((size_t)rr * W_ + cc) * DIM + ch] * w9[ch * 9 + kh * 3 + kw];
            }
        }
        o[k] = (s - bn_mean[ch]) * rsqrtf(bn_var[ch] + LN_EPS) * bn_g[ch] + bn_b[ch];
        g_x2[(size_t)p * DIM + ch] = o[k];
    }
    float s = o[0] + o[1] + o[2];
    float q = o[0] * o[0] + o[1] * o[1] + o[2] * o[2];
    blockReduce2_128(s, q);
    float mean = s * (1.f / DIM);
    float var = q * (1.f / DIM) - mean * mean;
    float rs = rsqrtf(var + LN_EPS);
    __half* outp = g_hA + (size_t)p * DIM;
    #pragma unroll
    for (int k = 0; k < 3; k++) {
        int ch = threadIdx.x + k * 128;
        outp[ch] = __float2half((o[k] - mean) * rs * ln_g[ch] + ln_b[ch]);
    }
}

// ---------------- launch ----------------
#define ATTN_SMEM (4 * UNIT_HALVES * 2 + 4 * 49 * 4 + 16)
extern "C" void kernel_launch(void* const* d_in, const int* in_sizes, int n_in,
                              void* d_out, int out_size) {
    const float* x       = (const float*)d_in[0];
    const float* ln1_g   = (const float*)d_in[1];
    const float* ln1_b   = (const float*)d_in[2];
    const float* qkv_w   = (const float*)d_in[3];
    const float* qkv_b   = (const float*)d_in[4];
    const float* proj_w  = (const float*)d_in[5];
    const float* proj_b  = (const float*)d_in[6];
    const float* attn_b  = (const float*)d_in[7];
    const float* conv_w  = (const float*)d_in[8];
    const float* bn_g    = (const float*)d_in[9];
    const float* bn_b    = (const float*)d_in[10];
    const float* bn_mean = (const float*)d_in[11];
    const float* bn_var  = (const float*)d_in[12];
    const float* ln2_g   = (const float*)d_in[13];
    const float* ln2_b   = (const float*)d_in[14];
    const float* fc1_w   = (const float*)d_in[15];
    const float* fc1_b   = (const float*)d_in[16];
    const float* fc2_w   = (const float*)d_in[17];
    const float* fc2_b   = (const float*)d_in[18];
    float* out = (float*)d_out;

    __half *phA, *phB, *phW;
    float *px1, *px2;
    cudaGetSymbolAddress((void**)&phA, g_hA);
    cudaGetSymbolAddress((void**)&phB, g_hB);
    cudaGetSymbolAddress((void**)&phW, g_hw);
    cudaGetSymbolAddress((void**)&px1, g_x1);
    cudaGetSymbolAddress((void**)&px2, g_x2);

    cudaFuncSetAttribute(attn_mma, cudaFuncAttributeMaxDynamicSharedMemorySize, ATTN_SMEM);

    // 0. all weight transposes (f32 -> half, (N,K) layout), one launch
    transpose_all<<<1728, dim3(32, 8)>>>(qkv_w, proj_w, fc1_w, fc2_w, phW);

    // 1. LN1 + window partition -> hA (half)
    ln1_win_kernel<<<TOK, 128>>>(x, ln1_g, ln1_b);

    // 2. QKV GEMM -> hB (half)
    mma_gemm<0><<<dim3(1152 / 128, (TOK + 127) / 128), 256>>>(
        phA, phW + WT_QKV_OFF, qkv_b, nullptr, (float*)phB, TOK, 1152, 384);

    // 3. attention (tensor-core) -> hA (half)
    attn_mma<<<NWIN * NHEADS / AUNITS, 256, ATTN_SMEM>>>(attn_b);

    // 4. proj GEMM + un-window + residual -> x1 (f32)
    mma_gemm<1><<<dim3(384 / 128, (TOK + 127) / 128), 256>>>(
        phA, phW + WT_PROJ_OFF, proj_b, x, px1, TOK, 384, 384);

    // 5. depthwise conv + BN -> x2 (f32), fused LN2 -> hA (half)
    conv_bn_ln_kernel<<<BATCH * HW, 128>>>(conv_w, bn_g, bn_b, bn_mean, bn_var,
                                           ln2_g, ln2_b);

    // 6. FC1 + GELU -> hB (half h1)
    mma_gemm<2><<<dim3(1536 / 128, (BATCH * HW) / 128), 256>>>(
        phA, phW + WT_FC1_OFF, fc1_b, nullptr, (float*)phB, BATCH * HW, 1536, 384);

    // 7. FC2 + residual -> d_out (f32)
    mma_gemm<3><<<dim3(384 / 128, (BATCH * HW) / 128), 256>>>(
        phB, phW + WT_FC2_OFF, fc2_b, px2, out, BATCH * HW, 384, 1536);
}

// round 17
// speedup vs baseline: 1.8769x; 1.0091x over previous
#include <cuda_runtime.h>
#include <cuda_fp16.h>
#include <math.h>
#include <stdint.h>

#define H_ 64
#define W_ 64
#define DIM 384
#define NHEADS 12
#define HDIM 32
#define WSZ 7
#define NTOK 49
#define NWIN 400
#define TOK 19600
#define BATCH 4
#define HW 4096
#define HID 1536
#define ATTN_SCALE 0.17677669529663689f
#define LN_EPS 1e-5f

// ---------------- scratch (device globals) ----------------
__device__ __half g_hA[TOK * DIM];
__device__ __half g_hB[(size_t)BATCH * HW * HID > (size_t)TOK * 3 * DIM
                       ? (size_t)BATCH * HW * HID : (size_t)TOK * 3 * DIM];
__device__ float g_x1[BATCH * HW * DIM];
__device__ float g_x2[BATCH * HW * DIM];
__device__ float g_bt[NHEADS * 64 * 64];   // masked bias table, -1e30 outside 49x49
#define WT_QKV_OFF 0
#define WT_PROJ_OFF (1152*384)
#define WT_FC1_OFF  (WT_PROJ_OFF + 384*384)
#define WT_FC2_OFF  (WT_FC1_OFF + 1536*384)
__device__ __half g_hw[WT_FC2_OFF + 384*1536];

// ---------------- helpers ----------------
__device__ __forceinline__ uint32_t smem_u32(const void* p) {
    uint32_t a;
    asm("{ .reg .u64 t; cvta.to.shared.u64 t, %1; cvt.u32.u64 %0, t; }" : "=r"(a) : "l"(p));
    return a;
}
__device__ __forceinline__ void cp_async16(uint32_t dst, const void* src, int srcbytes) {
    asm volatile("cp.async.cg.shared.global [%0], [%1], 16, %2;"
                 :: "r"(dst), "l"(src), "r"(srcbytes));
}
#define CP_COMMIT() asm volatile("cp.async.commit_group;" ::: "memory")
#define CP_WAIT2()  asm volatile("cp.async.wait_group 2;" ::: "memory")
#define CP_WAIT1()  asm volatile("cp.async.wait_group 1;" ::: "memory")
#define CP_WAIT0()  asm volatile("cp.async.wait_group 0;" ::: "memory")

__device__ __forceinline__ void mma_f16(float* c, const uint32_t* a, const uint32_t* b) {
    asm volatile(
        "mma.sync.aligned.m16n8k16.row.col.f32.f16.f16.f32 "
        "{%0,%1,%2,%3}, {%4,%5,%6,%7}, {%8,%9}, {%0,%1,%2,%3};"
        : "+f"(c[0]), "+f"(c[1]), "+f"(c[2]), "+f"(c[3])
        : "r"(a[0]), "r"(a[1]), "r"(a[2]), "r"(a[3]), "r"(b[0]), "r"(b[1]));
}
__device__ __forceinline__ uint32_t packh2(float x, float y) {
    __half2 h = __floats2half2_rn(x, y);
    return *(uint32_t*)&h;
}

// ---------------- fp16 tensor-core GEMM, 3-stage cp.async pipeline ----------
#define BM 128
#define BN 128
#define BK 32
#define PADH 40
#define ABUF (BM * PADH)
#define BBUF (BN * PADH)
#define GEMM_SMEM (3 * (ABUF + BBUF) * 2)
template <int EPI>
__global__ __launch_bounds__(256)
void mma_gemm(const __half* __restrict__ A, const __half* __restrict__ WT,
              const float* __restrict__ bias, const float* __restrict__ res,
              float* __restrict__ C, int M, int N, int K) {
    extern __shared__ __half gsm[];
    __half* Asl = gsm;               // 3 * ABUF
    __half* Bsl = gsm + 3 * ABUF;    // 3 * BBUF
    uint32_t sAb = smem_u32(Asl), sBb = smem_u32(Bsl);
    int tid = threadIdx.x;
    int lane = tid & 31, wid = tid >> 5;
    int wm = wid & 1, wn = wid >> 1;
    int row0 = blockIdx.y * BM, col0 = blockIdx.x * BN;
    int g4 = lane >> 2, t4 = lane & 3;

    float acc[4][4][4] = {};
    int nk = K / BK;

    #define STAGE(buf, k0) do { \
        int _k0 = (k0); \
        uint32_t _sa = sAb + (uint32_t)(buf) * (ABUF * 2u); \
        uint32_t _sb = sBb + (uint32_t)(buf) * (BBUF * 2u); \
        _Pragma("unroll") \
        for (int i = 0; i < 2; i++) { \
            int idx = tid + i * 256; \
            int r = idx >> 2, c = idx & 3; \
            int gr = row0 + r; \
            uint32_t d = _sa + (uint32_t)(r * PADH + c * 8) * 2u; \
            cp_async16(d, A + (size_t)gr * K + _k0 + c * 8, gr < M ? 16 : 0); \
        } \
        _Pragma("unroll") \
        for (int i = 0; i < 2; i++) { \
            int idx = tid + i * 256; \
            int r = idx >> 2, c = idx & 3; \
            uint32_t d = _sb + (uint32_t)(r * PADH + c * 8) * 2u; \
            cp_async16(d, WT + (size_t)(col0 + r) * K + _k0 + c * 8, 16); \
        } \
        CP_COMMIT(); \
    } while (0)

    STAGE(0, 0);
    STAGE(1, BK);
    for (int t = 0; t < nk; t++) {
        int buf = t % 3;
        if (t + 2 < nk) { STAGE((t + 2) % 3, (t + 2) * BK); CP_WAIT2(); }
        else if (t + 1 < nk) { CP_WAIT1(); }
        else { CP_WAIT0(); }
        __syncthreads();

        const __half* as = Asl + buf * ABUF;
        const __half* bs = Bsl + buf * BBUF;
        #pragma unroll
        for (int kk = 0; kk < BK; kk += 16) {
            uint32_t af[4][4], bf[4][2];
            #pragma unroll
            for (int mi = 0; mi < 4; mi++) {
                int m = wm * 64 + mi * 16 + g4;
                af[mi][0] = *(const uint32_t*)(as + m * PADH + kk + 2 * t4);
                af[mi][1] = *(const uint32_t*)(as + (m + 8) * PADH + kk + 2 * t4);
                af[mi][2] = *(const uint32_t*)(as + m * PADH + kk + 2 * t4 + 8);
                af[mi][3] = *(const uint32_t*)(as + (m + 8) * PADH + kk + 2 * t4 + 8);
            }
            #pragma unroll
            for (int nj = 0; nj < 4; nj++) {
                int n = wn * 32 + nj * 8 + g4;
                bf[nj][0] = *(const uint32_t*)(bs + n * PADH + kk + 2 * t4);
                bf[nj][1] = *(const uint32_t*)(bs + n * PADH + kk + 2 * t4 + 8);
            }
            #pragma unroll
            for (int mi = 0; mi < 4; mi++)
                #pragma unroll
                for (int nj = 0; nj < 4; nj++)
                    mma_f16(acc[mi][nj], af[mi], bf[nj]);
        }
        __syncthreads();
    }

    __half* Ch = (__half*)C;
    #pragma unroll
    for (int mi = 0; mi < 4; mi++) {
        #pragma unroll
        for (int half_ = 0; half_ < 2; half_++) {
            int r = row0 + wm * 64 + mi * 16 + g4 + half_ * 8;
            if (r >= M) continue;
            size_t obase = 0;
            bool valid = true;
            if (EPI == 1) {
                int w = r / NTOK, n = r % NTOK;
                int bb = w / 100, wh = (w / 10) % 10, ww = w % 10;
                int rr = wh * WSZ + n / WSZ;
                int cc = ww * WSZ + n % WSZ;
                valid = (rr < H_) && (cc < W_);
                if (valid) obase = ((size_t)bb * HW + (size_t)rr * W_ + cc) * DIM;
            }
            #pragma unroll
            for (int nj = 0; nj < 4; nj++) {
                int cn = col0 + wn * 32 + nj * 8 + 2 * t4;
                float v0 = acc[mi][nj][half_ * 2 + 0] + bias[cn];
                float v1 = acc[mi][nj][half_ * 2 + 1] + bias[cn + 1];
                if (EPI == 0) {
                    *(__half2*)(Ch + (size_t)r * N + cn) = __floats2half2_rn(v0, v1);
                } else if (EPI == 1) {
                    if (valid) {
                        float2 rr2 = *(const float2*)(res + obase + cn);
                        *(float2*)(C + obase + cn) = make_float2(v0 + rr2.x, v1 + rr2.y);
                    }
                } else if (EPI == 2) {
                    v0 = 0.5f * v0 * (1.f + erff(v0 * 0.70710678118654752f));
                    v1 = 0.5f * v1 * (1.f + erff(v1 * 0.70710678118654752f));
                    *(__half2*)(Ch + (size_t)r * N + cn) = __floats2half2_rn(v0, v1);
                } else {
                    float2 rr2 = *(const float2*)(res + (size_t)r * N + cn);
                    *(float2*)(C + (size_t)r * N + cn) = make_float2(v0 + rr2.x, v1 + rr2.y);
                }
            }
        }
    }
}

// ------- merged weight transpose + attention bias table, one launch ---------
__global__ void transpose_all(const float* __restrict__ qkv_w,
                              const float* __restrict__ proj_w,
                              const float* __restrict__ fc1_w,
                              const float* __restrict__ fc2_w,
                              const float* __restrict__ attn_b,
                              __half* __restrict__ wt) {
    __shared__ float t[32][33];
    int b = blockIdx.x;
    int tx = threadIdx.x, ty = threadIdx.y;
    if (b >= 1728) {   // bias table: 12*64*64 entries, -1e30 outside 49x49
        int e = (b - 1728) * 256 + ty * 32 + tx;
        int h = e >> 12, rc = e & 4095;
        int r = rc >> 6, c = rc & 63;
        float v = -1e30f;
        if (r < NTOK && c < NTOK) {
            int dr = abs(r / WSZ - c / WSZ);
            int dc = abs(r % WSZ - c % WSZ);
            v = attn_b[h * NTOK + dr * WSZ + dc];
        }
        g_bt[e] = v;
        return;
    }
    const float* W; __half* WT; int K, N, tt;
    if (b < 432)       { W = qkv_w;  WT = wt + WT_QKV_OFF;  K = 384;  N = 1152; tt = b; }
    else if (b < 576)  { W = proj_w; WT = wt + WT_PROJ_OFF; K = 384;  N = 384;  tt = b - 432; }
    else if (b < 1152) { W = fc1_w;  WT = wt + WT_FC1_OFF;  K = 384;  N = 1536; tt = b - 576; }
    else               { W = fc2_w;  WT = wt + WT_FC2_OFF;  K = 1536; N = 384;  tt = b - 1152; }
    int nx = N / 32;
    int n0 = (tt % nx) * 32, k0 = (tt / nx) * 32;
    #pragma unroll
    for (int i = 0; i < 32; i += 8)
        t[ty + i][tx] = W[(size_t)(k0 + ty + i) * N + n0 + tx];
    __syncthreads();
    #pragma unroll
    for (int i = 0; i < 32; i += 8)
        WT[(size_t)(n0 + ty + i) * K + k0 + tx] = __float2half(t[tx][ty + i]);
}

// ---------------- block reduce (128 threads) ----------------
__device__ __forceinline__ void blockReduce2_128(float& s, float& q) {
    __shared__ float sh[8];
    int lane = threadIdx.x & 31, warp = threadIdx.x >> 5;
    #pragma unroll
    for (int o = 16; o > 0; o >>= 1) {
        s += __shfl_down_sync(0xffffffffu, s, o);
        q += __shfl_down_sync(0xffffffffu, q, o);
    }
    if (lane == 0) { sh[warp] = s; sh[4 + warp] = q; }
    __syncthreads();
    if (threadIdx.x == 0) {
        float a = 0.f, b = 0.f;
        #pragma unroll
        for (int i = 0; i < 4; i++) { a += sh[i]; b += sh[4 + i]; }
        sh[0] = a; sh[4] = b;
    }
    __syncthreads();
    s = sh[0]; q = sh[4];
    __syncthreads();
}

// ---------------- LN1 + window gather -> half ----------------
__global__ void ln1_win_kernel(const float* __restrict__ x,
                               const float* __restrict__ g,
                               const float* __restrict__ b) {
    int t = blockIdx.x;
    int w = t / NTOK, n = t % NTOK;
    int bb = w / 100, wh = (w / 10) % 10, ww = w % 10;
    int r = wh * WSZ + n / WSZ;
    int c = ww * WSZ + n % WSZ;
    __half* out = g_hA + (size_t)t * DIM;
    if (r >= H_ || c >= W_) {
        for (int ch = threadIdx.x; ch < DIM; ch += 128) out[ch] = __float2half(b[ch]);
        return;
    }
    const float* row = x + ((size_t)bb * HW + (size_t)r * W_ + c) * DIM;
    float v0 = row[threadIdx.x];
    float v1 = row[threadIdx.x + 128];
    float v2 = row[threadIdx.x + 256];
    float s = v0 + v1 + v2;
    float q = v0 * v0 + v1 * v1 + v2 * v2;
    blockReduce2_128(s, q);
    float mean = s * (1.f / DIM);
    float var = q * (1.f / DIM) - mean * mean;
    float rs = rsqrtf(var + LN_EPS);
    int ch = threadIdx.x;
    out[ch]       = __float2half((v0 - mean) * rs * g[ch]       + b[ch]);
    out[ch + 128] = __float2half((v1 - mean) * rs * g[ch + 128] + b[ch + 128]);
    out[ch + 256] = __float2half((v2 - mean) * rs * g[ch + 256] + b[ch + 256]);
}

// ---------------- attention via mma.sync: warp-pair per (window, head) ------
// bias+mask via precomputed g_bt table (L2-resident); K pad rows zeroed so
// valid-row scores stay finite (garbage*0 + table works; garbage+NaN wouldn't).
#define AUNITS 4
#define UNIT_HALVES 7424   // Qs 64x40 + Ks 64x40 + Vt 32x72
__global__ __launch_bounds__(256)
void attn_mma() {
    extern __shared__ __half smh[];
    int tid = threadIdx.x;
    int unit = tid >> 6;
    int u_tid = tid & 63;
    int lane = tid & 31;
    int wh = (tid >> 5) & 1;
    int g4 = lane >> 2, t4 = lane & 3;
    int gidx = blockIdx.x * AUNITS + unit;
    int w = gidx / NHEADS, h = gidx % NHEADS;

    __half* Qs = smh + unit * UNIT_HALVES;
    __half* Ks = Qs + 2560;
    __half* Vt = Ks + 2560;           // 32 rows (d) x 72 halves (m + pad)

    // zero V's padded m-columns (halves 48..63) AND K's pad rows 49..63.
    for (int i = u_tid; i < 256; i += 64) {
        int row = i >> 3, wc = 24 + (i & 7);
        ((uint32_t*)Vt)[row * 36 + wc] = 0u;
    }
    for (int i = u_tid; i < 300; i += 64) {   // 15 rows x 20 words
        int rr = 49 + i / 20, cc = i % 20;
        ((uint32_t*)Ks)[rr * 20 + cc] = 0u;
    }
    __syncthreads();

    // fill Q, K (row n, 32 halves) and V transposed (row d, col m)
    const uint32_t* qkvw = (const uint32_t*)g_hB;
    for (int i = u_tid; i < NTOK * 16; i += 64) {
        int n = i >> 4, d2 = i & 15;
        size_t base = ((size_t)(w * NTOK + n) * 1152 + h * 96) >> 1;
        uint32_t qw = qkvw[base + d2];
        uint32_t kw = qkvw[base + 16 + d2];
        uint32_t vw = qkvw[base + 32 + d2];
        ((uint32_t*)Qs)[n * 20 + d2] = qw;
        ((uint32_t*)Ks)[n * 20 + d2] = kw;
        __half2 vv = *(__half2*)&vw;
        Vt[(2 * d2) * 72 + n] = __low2half(vv);
        Vt[(2 * d2 + 1) * 72 + n] = __high2half(vv);
    }
    __syncthreads();

    // ---- scores: 2 mi-tiles x 8 nj-tiles, K=32 ----
    const uint32_t* Qw = (const uint32_t*)Qs;
    const uint32_t* Kw = (const uint32_t*)Ks;
    float s[2][8][4] = {};
    #pragma unroll
    for (int kk = 0; kk < 2; kk++) {
        uint32_t a[2][4], b[8][2];
        #pragma unroll
        for (int mi = 0; mi < 2; mi++) {
            int r = wh * 32 + mi * 16 + g4;
            a[mi][0] = Qw[r * 20 + kk * 8 + t4];
            a[mi][1] = Qw[(r + 8) * 20 + kk * 8 + t4];
            a[mi][2] = Qw[r * 20 + kk * 8 + t4 + 4];
            a[mi][3] = Qw[(r + 8) * 20 + kk * 8 + t4 + 4];
        }
        #pragma unroll
        for (int nj = 0; nj < 8; nj++) {
            int n = nj * 8 + g4;
            b[nj][0] = Kw[n * 20 + kk * 8 + t4];
            b[nj][1] = Kw[n * 20 + kk * 8 + t4 + 4];
        }
        #pragma unroll
        for (int mi = 0; mi < 2; mi++)
            #pragma unroll
            for (int nj = 0; nj < 8; nj++)
                mma_f16(s[mi][nj], a[mi], b[nj]);
    }

    // ---- bias + mask + softmax via table ----
    const float* tb = g_bt + h * 4096;
    #pragma unroll
    for (int mi = 0; mi < 2; mi++) {
        #pragma unroll
        for (int hf = 0; hf < 2; hf++) {
            int row = wh * 32 + mi * 16 + hf * 8 + g4;
            bool rowok = row < NTOK;
            const float* trow = tb + row * 64 + 2 * t4;
            float mx = -1e30f;
            #pragma unroll
            for (int nj = 0; nj < 8; nj++) {
                float2 bv = *(const float2*)(trow + nj * 8);
                float v0 = s[mi][nj][hf * 2 + 0] * ATTN_SCALE + bv.x;
                float v1 = s[mi][nj][hf * 2 + 1] * ATTN_SCALE + bv.y;
                s[mi][nj][hf * 2 + 0] = v0;
                s[mi][nj][hf * 2 + 1] = v1;
                mx = fmaxf(mx, fmaxf(v0, v1));
            }
            mx = fmaxf(mx, __shfl_xor_sync(0xffffffffu, mx, 1));
            mx = fmaxf(mx, __shfl_xor_sync(0xffffffffu, mx, 2));
            if (mx < -1e29f) mx = 0.f;
            float sum = 0.f;
            #pragma unroll
            for (int nj = 0; nj < 8; nj++) {
                float e0 = __expf(s[mi][nj][hf * 2 + 0] - mx);
                float e1 = __expf(s[mi][nj][hf * 2 + 1] - mx);
                s[mi][nj][hf * 2 + 0] = e0;
                s[mi][nj][hf * 2 + 1] = e1;
                sum += e0 + e1;
            }
            sum += __shfl_xor_sync(0xffffffffu, sum, 1);
            sum += __shfl_xor_sync(0xffffffffu, sum, 2);
            float inv = rowok ? 1.f / sum : 0.f;
            #pragma unroll
            for (int nj = 0; nj < 8; nj++) {
                s[mi][nj][hf * 2 + 0] *= inv;
                s[mi][nj][hf * 2 + 1] *= inv;
            }
        }
    }

    // ---- O = P @ V ----
    float o[2][4][4] = {};
    const uint32_t* Vw = (const uint32_t*)Vt;
    #pragma unroll
    for (int kkA = 0; kkA < 4; kkA++) {
        uint32_t b[4][2];
        #pragma unroll
        for (int njd = 0; njd < 4; njd++) {
            int d = njd * 8 + g4;
            b[njd][0] = Vw[d * 36 + kkA * 8 + t4];
            b[njd][1] = Vw[d * 36 + kkA * 8 + t4 + 4];
        }
        #pragma unroll
        for (int mi = 0; mi < 2; mi++) {
            uint32_t a[4];
            a[0] = packh2(s[mi][2 * kkA][0],     s[mi][2 * kkA][1]);
            a[1] = packh2(s[mi][2 * kkA][2],     s[mi][2 * kkA][3]);
            a[2] = packh2(s[mi][2 * kkA + 1][0], s[mi][2 * kkA + 1][1]);
            a[3] = packh2(s[mi][2 * kkA + 1][2], s[mi][2 * kkA + 1][3]);
            #pragma unroll
            for (int njd = 0; njd < 4; njd++)
                mma_f16(o[mi][njd], a, b[njd]);
        }
    }

    // ---- store valid rows ----
    #pragma unroll
    for (int mi = 0; mi < 2; mi++) {
        #pragma unroll
        for (int hf = 0; hf < 2; hf++) {
            int row = wh * 32 + mi * 16 + hf * 8 + g4;
            if (row >= NTOK) continue;
            __half* dst = g_hA + ((size_t)(w * NTOK + row)) * DIM + h * HDIM;
            #pragma unroll
            for (int njd = 0; njd < 4; njd++) {
                int d = njd * 8 + 2 * t4;
                *(__half2*)(dst + d) =
                    __floats2half2_rn(o[mi][njd][hf * 2 + 0], o[mi][njd][hf * 2 + 1]);
            }
        }
    }
}

// ---------------- depthwise 3x3 conv + BN + fused LN2 (known-good) ----------
__global__ void conv_bn_ln_kernel(const float* __restrict__ w9,
                                  const float* __restrict__ bn_g,
                                  const float* __restrict__ bn_b,
                                  const float* __restrict__ bn_mean,
                                  const float* __restrict__ bn_var,
                                  const float* __restrict__ ln_g,
                                  const float* __restrict__ ln_b) {
    int p = blockIdx.x;
    int bb = p >> 12;
    int pos = p & 4095;
    int r = pos >> 6, c = pos & 63;
    const float* base = g_x1 + (size_t)bb * HW * DIM;
    float o[3];
    #pragma unroll
    for (int k = 0; k < 3; k++) {
        int ch = threadIdx.x + k * 128;
        float s = 0.f;
        #pragma unroll
        for (int kh = 0; kh < 3; kh++) {
            int rr = r + kh - 1;
            if (rr < 0 || rr >= H_) continue;
            #pragma unroll
            for (int kw = 0; kw < 3; kw++) {
                int cc = c + kw - 1;
                if (cc < 0 || cc >= W_) continue;
                s += base[((size_t)rr * W_ + cc) * DIM + ch] * w9[ch * 9 + kh * 3 + kw];
            }
        }
        o[k] = (s - bn_mean[ch]) * rsqrtf(bn_var[ch] + LN_EPS) * bn_g[ch] + bn_b[ch];
        g_x2[(size_t)p * DIM + ch] = o[k];
    }
    float s = o[0] + o[1] + o[2];
    float q = o[0] * o[0] + o[1] * o[1] + o[2] * o[2];
    blockReduce2_128(s, q);
    float mean = s * (1.f / DIM);
    float var = q * (1.f / DIM) - mean * mean;
    float rs = rsqrtf(var + LN_EPS);
    __half* outp = g_hA + (size_t)p * DIM;
    #pragma unroll
    for (int k = 0; k < 3; k++) {
        int ch = threadIdx.x + k * 128;
        outp[ch] = __float2half((o[k] - mean) * rs * ln_g[ch] + ln_b[ch]);
    }
}

// ---------------- launch ----------------
#define ATTN_SMEM (4 * UNIT_HALVES * 2 + 16)
extern "C" void kernel_launch(void* const* d_in, const int* in_sizes, int n_in,
                              void* d_out, int out_size) {
    const float* x       = (const float*)d_in[0];
    const float* ln1_g   = (const float*)d_in[1];
    const float* ln1_b   = (const float*)d_in[2];
    const float* qkv_w   = (const float*)d_in[3];
    const float* qkv_b   = (const float*)d_in[4];
    const float* proj_w  = (const float*)d_in[5];
    const float* proj_b  = (const float*)d_in[6];
    const float* attn_b  = (const float*)d_in[7];
    const float* conv_w  = (const float*)d_in[8];
    const float* bn_g    = (const float*)d_in[9];
    const float* bn_b    = (const float*)d_in[10];
    const float* bn_mean = (const float*)d_in[11];
    const float* bn_var  = (const float*)d_in[12];
    const float* ln2_g   = (const float*)d_in[13];
    const float* ln2_b   = (const float*)d_in[14];
    const float* fc1_w   = (const float*)d_in[15];
    const float* fc1_b   = (const float*)d_in[16];
    const float* fc2_w   = (const float*)d_in[17];
    const float* fc2_b   = (const float*)d_in[18];
    float* out = (float*)d_out;

    __half *phA, *phB, *phW;
    float *px1, *px2;
    cudaGetSymbolAddress((void**)&phA, g_hA);
    cudaGetSymbolAddress((void**)&phB, g_hB);
    cudaGetSymbolAddress((void**)&phW, g_hw);
    cudaGetSymbolAddress((void**)&px1, g_x1);
    cudaGetSymbolAddress((void**)&px2, g_x2);

    cudaFuncSetAttribute(attn_mma, cudaFuncAttributeMaxDynamicSharedMemorySize, ATTN_SMEM);
    cudaFuncSetAttribute(mma_gemm<0>, cudaFuncAttributeMaxDynamicSharedMemorySize, GEMM_SMEM);
    cudaFuncSetAttribute(mma_gemm<1>, cudaFuncAttributeMaxDynamicSharedMemorySize, GEMM_SMEM);
    cudaFuncSetAttribute(mma_gemm<2>, cudaFuncAttributeMaxDynamicSharedMemorySize, GEMM_SMEM);
    cudaFuncSetAttribute(mma_gemm<3>, cudaFuncAttributeMaxDynamicSharedMemorySize, GEMM_SMEM);

    // 0. weight transposes + bias table (1728 + 192 blocks)
    transpose_all<<<1920, dim3(32, 8)>>>(qkv_w, proj_w, fc1_w, fc2_w, attn_b, phW);

    // 1. LN1 + window partition -> hA (half)
    ln1_win_kernel<<<TOK, 128>>>(x, ln1_g, ln1_b);

    // 2. QKV GEMM -> hB (half)
    mma_gemm<0><<<dim3(1152 / 128, (TOK + 127) / 128), 256, GEMM_SMEM>>>(
        phA, phW + WT_QKV_OFF, qkv_b, nullptr, (float*)phB, TOK, 1152, 384);

    // 3. attention (tensor-core) -> hA (half)
    attn_mma<<<NWIN * NHEADS / AUNITS, 256, ATTN_SMEM>>>();

    // 4. proj GEMM + un-window + residual -> x1 (f32)
    mma_gemm<1><<<dim3(384 / 128, (TOK + 127) / 128), 256, GEMM_SMEM>>>(
        phA, phW + WT_PROJ_OFF, proj_b, x, px1, TOK, 384, 384);

    // 5. depthwise conv + BN -> x2 (f32), fused LN2 -> hA (half)
    conv_bn_ln_kernel<<<BATCH * HW, 128>>>(conv_w, bn_g, bn_b, bn_mean, bn_var,
                                           ln2_g, ln2_b);

    // 6. FC1 + GELU -> hB (half h1)
    mma_gemm<2><<<dim3(1536 / 128, (BATCH * HW) / 128), 256, GEMM_SMEM>>>(
        phA, phW + WT_FC1_OFF, fc1_b, nullptr, (float*)phB, BATCH * HW, 1536, 384);

    // 7. FC2 + residual -> d_out (f32)
    mma_gemm<3><<<dim3(384 / 128, (BATCH * HW) / 128), 256, GEMM_SMEM>>>(
        phB, phW + WT_FC2_OFF, fc2_b, px2, out, BATCH * HW, 384, 1536);
}